// round 17
// baseline (speedup 1.0000x reference)
#include <cuda_runtime.h>

// PixCorr: per-row Pearson correlation over [256, 196608] fp32 rows, then
// mean over rows.
//
// Occupancy experiment on the champion two-kernel PDL structure:
//  - Row kernel: 296 CTAs x 512 threads (2 CTAs/SM -> 64 warps/SM, occ 100%,
//    exactly one wave on 148 SMs). Flat contiguous static partition of the
//    whole TOTVEC stream (R8 machinery): each CTA streams one long
//    uninterrupted span (~83 iters/thread, plain cached float4 loads),
//    block-reduces each of its <=2 row-sub-spans into g_part[cta*SLOTS+slot].
//  - Mean kernel (PDL, 256 threads): after cudaGridDependencySynchronize,
//    thread r assembles row r's 5 sums from its <=3 contributing CTAs in
//    fixed order, computes corr, block-reduces the mean, writes d_out[0].

#define NROWS    256
#define D_ELEMS  196608                      // 3*256*256
#define NVEC     (D_ELEMS / 4)               // 49152 float4 per row
#define TOTVEC   ((unsigned long long)NROWS * NVEC)  // 12,582,912
#define GRID     296                         // 2 CTAs per SM, one wave
#define THREADS  512
#define SLOTS    3
#define EPS      1e-6f

__device__ float g_part[GRID * SLOTS][5];

__device__ __forceinline__ float warp_sum(float v) {
    v += __shfl_xor_sync(0xFFFFFFFFu, v, 16);
    v += __shfl_xor_sync(0xFFFFFFFFu, v, 8);
    v += __shfl_xor_sync(0xFFFFFFFFu, v, 4);
    v += __shfl_xor_sync(0xFFFFFFFFu, v, 2);
    v += __shfl_xor_sync(0xFFFFFFFFu, v, 1);
    return v;
}

__device__ __forceinline__ unsigned int span_start(unsigned int c) {
    return (unsigned int)(((unsigned long long)c * TOTVEC) / GRID);
}
__device__ __forceinline__ unsigned int cta_of(unsigned int v) {
    return (unsigned int)((((unsigned long long)v + 1ull) * GRID - 1ull) / TOTVEC);
}

__global__ __launch_bounds__(THREADS, 2)
void pixcorr_row_kernel(const float* __restrict__ preds,
                        const float* __restrict__ targets) {
    __shared__ float sh[5][THREADS / 32];
    const int lane = threadIdx.x & 31;
    const int wid  = threadIdx.x >> 5;
    const unsigned int c = blockIdx.x;

    const unsigned int span_lo = span_start(c);
    const unsigned int span_hi = span_start(c + 1);

    const float4* __restrict__ zall = reinterpret_cast<const float4*>(targets);
    const float4* __restrict__ ball = reinterpret_cast<const float4*>(preds);

    unsigned int pos  = span_lo;
    int          slot = 0;
    while (pos < span_hi) {
        const unsigned int row_end = (pos / NVEC + 1u) * NVEC;
        const unsigned int sub_end = (row_end < span_hi) ? row_end : span_hi;
        const int len = (int)(sub_end - pos);

        const float4* __restrict__ z4 = zall + pos;
        const float4* __restrict__ b4 = ball + pos;

        float sz = 0.f, sb = 0.f, szz = 0.f, sbb = 0.f, szb = 0.f;

        #pragma unroll 4
        for (int i = threadIdx.x; i < len; i += THREADS) {
            float4 zv = z4[i];
            float4 bv = b4[i];
            sz  += (zv.x + zv.y) + (zv.z + zv.w);
            sb  += (bv.x + bv.y) + (bv.z + bv.w);
            szz  = fmaf(zv.x, zv.x, fmaf(zv.y, zv.y, fmaf(zv.z, zv.z, fmaf(zv.w, zv.w, szz))));
            sbb  = fmaf(bv.x, bv.x, fmaf(bv.y, bv.y, fmaf(bv.z, bv.z, fmaf(bv.w, bv.w, sbb))));
            szb  = fmaf(zv.x, bv.x, fmaf(zv.y, bv.y, fmaf(zv.z, bv.z, fmaf(zv.w, bv.w, szb))));
        }

        sz  = warp_sum(sz);
        sb  = warp_sum(sb);
        szz = warp_sum(szz);
        sbb = warp_sum(sbb);
        szb = warp_sum(szb);

        if (lane == 0) {
            sh[0][wid] = sz;  sh[1][wid] = sb;
            sh[2][wid] = szz; sh[3][wid] = sbb; sh[4][wid] = szb;
        }
        __syncthreads();

        if (threadIdx.x < 32) {
            // THREADS/32 = 16 warps -> lanes 16..31 read garbage-free zeros
            float a0 = (lane < THREADS / 32) ? sh[0][lane] : 0.f;
            float a1 = (lane < THREADS / 32) ? sh[1][lane] : 0.f;
            float a2 = (lane < THREADS / 32) ? sh[2][lane] : 0.f;
            float a3 = (lane < THREADS / 32) ? sh[3][lane] : 0.f;
            float a4 = (lane < THREADS / 32) ? sh[4][lane] : 0.f;
            a0 = warp_sum(a0);
            a1 = warp_sum(a1);
            a2 = warp_sum(a2);
            a3 = warp_sum(a3);
            a4 = warp_sum(a4);
            if (lane == 0) {
                const int idx = (int)c * SLOTS + slot;
                g_part[idx][0] = a0;
                g_part[idx][1] = a1;
                g_part[idx][2] = a2;
                g_part[idx][3] = a3;
                g_part[idx][4] = a4;
            }
        }
        __syncthreads();

        slot++;
        pos = sub_end;
    }
}

__global__ void pixcorr_mean_kernel(float* __restrict__ out) {
    // PDL: wait for the row grid's completion + memory flush.
    cudaGridDependencySynchronize();

    const int lane = threadIdx.x & 31;
    const int wid  = threadIdx.x >> 5;

    // Thread r assembles row r from its contributing CTAs (fixed order).
    float corr = 0.f;
    {
        const unsigned int r  = threadIdx.x;      // 0..255
        const unsigned int v0 = r * NVEC;
        const unsigned int v1 = v0 + NVEC - 1u;
        const unsigned int c0 = cta_of(v0);
        const unsigned int c1 = cta_of(v1);
        float a0 = 0.f, a1 = 0.f, a2 = 0.f, a3 = 0.f, a4 = 0.f;
        for (unsigned int cc = c0; cc <= c1; cc++) {
            const unsigned int rf = span_start(cc) / NVEC;
            const int idx = (int)cc * SLOTS + (int)(r - rf);
            a0 += g_part[idx][0];
            a1 += g_part[idx][1];
            a2 += g_part[idx][2];
            a3 += g_part[idx][3];
            a4 += g_part[idx][4];
        }
        const float invD = 1.0f / (float)D_ELEMS;
        float cov = a4 - a0 * a1 * invD;
        float vz  = fmaxf(a2 - a0 * a0 * invD, 0.f);
        float vb  = fmaxf(a3 - a1 * a1 * invD, 0.f);
        corr = cov / (sqrtf(vz) * sqrtf(vb) + EPS);
    }

    corr = warp_sum(corr);
    __shared__ float sh[8];
    if (lane == 0) sh[wid] = corr;
    __syncthreads();
    if (threadIdx.x == 0) {
        float s = 0.f;
        #pragma unroll
        for (int i = 0; i < 8; i++) s += sh[i];
        out[0] = s * (1.0f / (float)NROWS);
    }
}

extern "C" void kernel_launch(void* const* d_in, const int* in_sizes, int n_in,
                              void* d_out, int out_size) {
    const float* preds   = (const float*)d_in[0];
    const float* targets = (const float*)d_in[1];
    float* out = (float*)d_out;

    pixcorr_row_kernel<<<GRID, THREADS>>>(preds, targets);

    cudaLaunchConfig_t cfg = {};
    cfg.gridDim  = dim3(1, 1, 1);
    cfg.blockDim = dim3(NROWS, 1, 1);
    cfg.dynamicSmemBytes = 0;
    cfg.stream = 0;
    cudaLaunchAttribute attr[1];
    attr[0].id = cudaLaunchAttributeProgrammaticStreamSerialization;
    attr[0].val.programmaticStreamSerializationAllowed = 1;
    cfg.attrs = attr;
    cfg.numAttrs = 1;

    cudaError_t e = cudaLaunchKernelEx(&cfg, pixcorr_mean_kernel, out);
    if (e != cudaSuccess) {
        pixcorr_mean_kernel<<<1, NROWS>>>(out);
    }
}